// round 13
// baseline (speedup 1.0000x reference)
#include <cuda_runtime.h>
#include <cstdint>

// Conv 3x3 SAME + ReLU, implicit GEMM, TF32 mma.sync.m16n8k8.
// Round 13: 2 CTAs/SM for cross-CTA latency hiding.
// BM=128, BN=128, BK=32, 256 threads (8 warps 2m x 4n, warp tile 64x32,
// 64 acc regs -> fits 128 regs -> 2 CTAs/SM = 16 warps/SM with independent
// barriers). 3-stage cp.async pipeline, XOR-SW128 swizzle (conflict-free
// stores + ldmatrix reads). Operands pre-converted to TF32(rna) scratch.

namespace {

constexpr int H    = 224;
constexpr int W    = 224;
constexpr int CIN  = 128;
constexpr int COUT = 256;
constexpr int KTOT = 1152;
constexpr int BM = 128, BN = 128, BK = 32;
constexpr int NT      = KTOT / BK;   // 36 stages, 4 per (kh,kw)
constexpr int STAGES  = 3;
constexpr int ROWB    = 128;         // 8 chunks of 16B; phys_chunk = c ^ (row&7)
constexpr int ABYTES  = BM * ROWB;                 // 16384
constexpr int BBYTES  = BN * ROWB;                 // 16384
constexpr int STAGE_BYTES = ABYTES + BBYTES;       // 32768
constexpr int SMEM_TOTAL  = STAGES * STAGE_BYTES;  // 98304 (x2 CTAs = 192KB/SM)

__device__ uint32_t Xc_g[H * W * CIN];      // TF32-converted X
__device__ uint32_t Wc_g[COUT * KTOT];      // TF32-converted W

__device__ __forceinline__ uint32_t f2tf32(float f) {
    uint32_t r;
    asm("cvt.rna.tf32.f32 %0, %1;" : "=r"(r) : "f"(f));
    return r;
}
__device__ __forceinline__ void cp_async16(uint32_t dst, const void* src, int src_sz) {
    asm volatile("cp.async.cg.shared.global [%0], [%1], 16, %2;"
                 :: "r"(dst), "l"(src), "r"(src_sz));
}
__device__ __forceinline__ void cp_commit() {
    asm volatile("cp.async.commit_group;" ::: "memory");
}
template <int N>
__device__ __forceinline__ void cp_wait() {
    asm volatile("cp.async.wait_group %0;" :: "n"(N) : "memory");
}
__device__ __forceinline__ void ldsm_x4(uint32_t* r, uint32_t addr) {
    asm volatile("ldmatrix.sync.aligned.m8n8.x4.shared.b16 {%0,%1,%2,%3}, [%4];"
                 : "=r"(r[0]), "=r"(r[1]), "=r"(r[2]), "=r"(r[3]) : "r"(addr));
}
__device__ __forceinline__ void mma_tf32(float* d, const uint32_t* a, const uint32_t* b) {
    asm volatile(
        "mma.sync.aligned.m16n8k8.row.col.f32.tf32.tf32.f32 "
        "{%0,%1,%2,%3}, {%4,%5,%6,%7}, {%8,%9}, {%0,%1,%2,%3};"
        : "+f"(d[0]), "+f"(d[1]), "+f"(d[2]), "+f"(d[3])
        : "r"(a[0]), "r"(a[1]), "r"(a[2]), "r"(a[3]), "r"(b[0]), "r"(b[1]));
}

// One stage's cp.async loads (256 threads).
// A: 128 rows x 8 chunks -> 2 thr/row, 4 chunks each.
// B: 128 rows x 8 chunks -> 2 thr/row, 4 chunks each.
// Conflict-free per 8-lane phase under p = c ^ (row&7).
__device__ __forceinline__ void load_stage(int t, uint32_t sbase, int tid,
                                           int ph, int pw, const uint32_t* wsrc) {
    const int slot = (t % STAGES);
    const int g  = t >> 2;               // kh*3 + kw
    const int kh = g / 3;
    const int kw = g - kh * 3;
    const int c0 = (t & 3) << 5;         // channel word base

    const int row = tid >> 1;            // 0..127 (same for A and B)
    const int rp  = row & 7;
    const int cc0 = (tid & 1) * 4;

    // ---- A ----
    const int h = ph + kh - 1;
    const int w = pw + kw - 1;
    const bool ok = ((unsigned)h < (unsigned)H) && ((unsigned)w < (unsigned)W);
    const int sz = ok ? 16 : 0;
    const uint32_t* asrc = Xc_g + (((long)(ok ? h : 0) * W + (ok ? w : 0)) * CIN + c0);
    const uint32_t ad = sbase + slot * STAGE_BYTES + row * ROWB;
    #pragma unroll
    for (int j = 0; j < 4; ++j) {
        const int c = cc0 + j;
        cp_async16(ad + ((c ^ rp) << 4), asrc + c * 4, sz);
    }

    // ---- B ----
    const uint32_t bd = sbase + slot * STAGE_BYTES + ABYTES + row * ROWB;
    const uint32_t* bsrc = wsrc + t * BK;
    #pragma unroll
    for (int j = 0; j < 4; ++j) {
        const int c = cc0 + j;
        cp_async16(bd + ((c ^ rp) << 4), bsrc + c * 4, 16);
    }

    cp_commit();
}

} // namespace

// ---- prologue: fp32 -> TF32(rna) conversion into __device__ scratch ----
__global__ __launch_bounds__(256)
void cvt_x_kernel(const float* __restrict__ src) {
    const int n4 = (H * W * CIN) / 4;
    int i = blockIdx.x * blockDim.x + threadIdx.x;
    if (i < n4) {
        float4 v = reinterpret_cast<const float4*>(src)[i];
        uint4 o = make_uint4(f2tf32(v.x), f2tf32(v.y), f2tf32(v.z), f2tf32(v.w));
        reinterpret_cast<uint4*>(Xc_g)[i] = o;
    }
}
__global__ __launch_bounds__(256)
void cvt_w_kernel(const float* __restrict__ src) {
    const int n4 = (COUT * KTOT) / 4;
    int i = blockIdx.x * blockDim.x + threadIdx.x;
    if (i < n4) {
        float4 v = reinterpret_cast<const float4*>(src)[i];
        uint4 o = make_uint4(f2tf32(v.x), f2tf32(v.y), f2tf32(v.z), f2tf32(v.w));
        reinterpret_cast<uint4*>(Wc_g)[i] = o;
    }
}

// ---- main GEMM ----
__global__ __launch_bounds__(256, 2)
void conv3x3_tc_kernel(float* __restrict__ Y) {
    extern __shared__ __align__(1024) uint32_t smem[];
    const uint32_t sbase = (uint32_t)__cvta_generic_to_shared(smem);

    const int tid  = threadIdx.x;
    const int warp = tid >> 5;
    const int lane = tid & 31;
    const int grp  = lane >> 2;
    const int tig  = lane & 3;

    const int mb = (warp & 1) * 64;      // 2 warps along m
    const int nb = (warp >> 1) * 32;     // 4 warps along n

    const int m0 = blockIdx.y * BM;
    const int n0 = blockIdx.x * BN;

    // ldmatrix lane geometry (XOR swizzle resolved per k-half in-loop).
    const int a_row = mb + (lane & 15);
    const int a_rp  = a_row & 7;
    const int a_h   = lane >> 4;
    const int b_row = nb + ((lane >> 4) << 3) + (lane & 7);
    const int b_rp  = b_row & 7;
    const int b_h   = (lane >> 3) & 1;

    // loader coordinates
    const int p  = m0 + (tid >> 1);
    const int ph = p / W;
    const int pw = p - ph * W;
    const uint32_t* wsrc = Wc_g + (long)(n0 + (tid >> 1)) * KTOT;

    float acc[4][4][4] = {};

    #pragma unroll
    for (int t = 0; t < STAGES - 1; ++t) load_stage(t, sbase, tid, ph, pw, wsrc);

    for (int t = 0; t < NT; ++t) {
        cp_wait<STAGES - 2>();
        __syncthreads();

        const int slot = (t % STAGES);
        const uint32_t astage = sbase + slot * STAGE_BYTES;
        const uint32_t bstage = astage + ABYTES;

        #pragma unroll
        for (int khalf = 0; khalf < 4; ++khalf) {
            const int q = khalf * 2;                       // 16B-chunk index
            const uint32_t a_co = (uint32_t)(((q + a_h) ^ a_rp) << 4);
            const uint32_t b_co = (uint32_t)(((q + b_h) ^ b_rp) << 4);

            uint32_t af[4][4], bf[4][2];
            #pragma unroll
            for (int mt = 0; mt < 4; ++mt)
                ldsm_x4(af[mt], astage + (uint32_t)((a_row + mt * 16) * ROWB) + a_co);
            #pragma unroll
            for (int np = 0; np < 2; ++np) {
                uint32_t tmp[4];
                ldsm_x4(tmp, bstage + (uint32_t)((b_row + np * 16) * ROWB) + b_co);
                bf[2 * np][0]     = tmp[0]; bf[2 * np][1]     = tmp[1];
                bf[2 * np + 1][0] = tmp[2]; bf[2 * np + 1][1] = tmp[3];
            }
            #pragma unroll
            for (int mt = 0; mt < 4; ++mt)
                #pragma unroll
                for (int nt = 0; nt < 4; ++nt)
                    mma_tf32(acc[mt][nt], af[mt], bf[nt]);
        }

        if (t + STAGES - 1 < NT) load_stage(t + STAGES - 1, sbase, tid, ph, pw, wsrc);
    }

    // ---- epilogue: ReLU + STG.64 ----
    #pragma unroll
    for (int mt = 0; mt < 4; ++mt) {
        const int r0 = m0 + mb + mt * 16 + grp;
        #pragma unroll
        for (int nt = 0; nt < 4; ++nt) {
            const int cb = n0 + nb + nt * 8 + tig * 2;
            float2 o0, o1;
            o0.x = fmaxf(acc[mt][nt][0], 0.f);
            o0.y = fmaxf(acc[mt][nt][1], 0.f);
            o1.x = fmaxf(acc[mt][nt][2], 0.f);
            o1.y = fmaxf(acc[mt][nt][3], 0.f);
            *reinterpret_cast<float2*>(Y + (long)r0 * COUT + cb)       = o0;
            *reinterpret_cast<float2*>(Y + (long)(r0 + 8) * COUT + cb) = o1;
        }
    }
}

extern "C" void kernel_launch(void* const* d_in, const int* in_sizes, int n_in,
                              void* d_out, int out_size) {
    const float* X  = (const float*)d_in[0];
    const float* Wt = (const float*)d_in[1];
    float* Y        = (float*)d_out;

    cudaFuncSetAttribute(conv3x3_tc_kernel,
                         cudaFuncAttributeMaxDynamicSharedMemorySize, SMEM_TOTAL);

    const int nx4 = (H * W * CIN) / 4;
    const int nw4 = (COUT * KTOT) / 4;
    cvt_x_kernel<<<(nx4 + 255) / 256, 256>>>(X);
    cvt_w_kernel<<<(nw4 + 255) / 256, 256>>>(Wt);

    dim3 grid(COUT / BN, (H * W) / BM);   // (2, 392)
    conv3x3_tc_kernel<<<grid, 256, SMEM_TOTAL>>>(Y);
}

// round 14
// speedup vs baseline: 1.1397x; 1.1397x over previous
#include <cuda_runtime.h>
#include <cstdint>

// Conv 3x3 SAME + ReLU, implicit GEMM, TF32 mma.sync.m16n8k8.
// Round 14: R11 config (best: BM=256,BN=128,BK=32, 512 thr, 16 warps 4m x 4n,
// 4-stage cp.async, XOR-SW128) + explicit fragment double-buffering:
// ldsm for k-half j+1 issued BEFORE the mma of k-half j, so smem latency is
// covered by tensor work instead of serializing (R11/R13 evidence: phases add).

namespace {

constexpr int H    = 224;
constexpr int W    = 224;
constexpr int CIN  = 128;
constexpr int COUT = 256;
constexpr int KTOT = 1152;
constexpr int BM = 256, BN = 128, BK = 32;
constexpr int NT      = KTOT / BK;   // 36 stages, 4 per (kh,kw)
constexpr int STAGES  = 4;
constexpr int ROWB    = 128;         // 8 chunks of 16B; phys_chunk = c ^ (row&7)
constexpr int ABYTES  = BM * ROWB;                 // 32768
constexpr int BBYTES  = BN * ROWB;                 // 16384
constexpr int STAGE_BYTES = ABYTES + BBYTES;       // 49152
constexpr int SMEM_TOTAL  = STAGES * STAGE_BYTES;  // 196608

__device__ uint32_t Xc_g[H * W * CIN];      // TF32-converted X
__device__ uint32_t Wc_g[COUT * KTOT];      // TF32-converted W

__device__ __forceinline__ uint32_t f2tf32(float f) {
    uint32_t r;
    asm("cvt.rna.tf32.f32 %0, %1;" : "=r"(r) : "f"(f));
    return r;
}
__device__ __forceinline__ void cp_async16(uint32_t dst, const void* src, int src_sz) {
    asm volatile("cp.async.cg.shared.global [%0], [%1], 16, %2;"
                 :: "r"(dst), "l"(src), "r"(src_sz));
}
__device__ __forceinline__ void cp_commit() {
    asm volatile("cp.async.commit_group;" ::: "memory");
}
template <int N>
__device__ __forceinline__ void cp_wait() {
    asm volatile("cp.async.wait_group %0;" :: "n"(N) : "memory");
}
__device__ __forceinline__ void ldsm_x4(uint32_t* r, uint32_t addr) {
    asm volatile("ldmatrix.sync.aligned.m8n8.x4.shared.b16 {%0,%1,%2,%3}, [%4];"
                 : "=r"(r[0]), "=r"(r[1]), "=r"(r[2]), "=r"(r[3]) : "r"(addr));
}
__device__ __forceinline__ void mma_tf32(float* d, const uint32_t* a, const uint32_t* b) {
    asm volatile(
        "mma.sync.aligned.m16n8k8.row.col.f32.tf32.tf32.f32 "
        "{%0,%1,%2,%3}, {%4,%5,%6,%7}, {%8,%9}, {%0,%1,%2,%3};"
        : "+f"(d[0]), "+f"(d[1]), "+f"(d[2]), "+f"(d[3])
        : "r"(a[0]), "r"(a[1]), "r"(a[2]), "r"(a[3]), "r"(b[0]), "r"(b[1]));
}

// One stage's cp.async loads (512 threads). Conflict-free under p = c ^ (row&7).
__device__ __forceinline__ void load_stage(int t, uint32_t sbase, int tid,
                                           int ph, int pw, const uint32_t* wsrc) {
    const int slot = t & (STAGES - 1);
    const int g  = t >> 2;               // kh*3 + kw
    const int kh = g / 3;
    const int kw = g - kh * 3;
    const int c0 = (t & 3) << 5;         // channel word base

    // ---- A: 256 rows x 8 chunks -> 2 thr/row, 4 chunks each ----
    const int h = ph + kh - 1;
    const int w = pw + kw - 1;
    const bool ok = ((unsigned)h < (unsigned)H) && ((unsigned)w < (unsigned)W);
    const int sz = ok ? 16 : 0;
    const uint32_t* asrc = Xc_g + (((long)(ok ? h : 0) * W + (ok ? w : 0)) * CIN + c0);

    const int arow = tid >> 1;
    const int arp  = arow & 7;
    const int ac0  = (tid & 1) * 4;
    const uint32_t ad = sbase + slot * STAGE_BYTES + arow * ROWB;
    #pragma unroll
    for (int j = 0; j < 4; ++j) {
        const int c = ac0 + j;
        cp_async16(ad + ((c ^ arp) << 4), asrc + c * 4, sz);
    }

    // ---- B: 128 rows x 8 chunks -> 4 thr/row, 2 chunks each ----
    const int brow = tid >> 2;
    const int brp  = brow & 7;
    const int bc0  = (tid & 3) * 2;
    const uint32_t bd = sbase + slot * STAGE_BYTES + ABYTES + brow * ROWB;
    const uint32_t* bsrc = wsrc + t * BK;
    #pragma unroll
    for (int j = 0; j < 2; ++j) {
        const int c = bc0 + j;
        cp_async16(bd + ((c ^ brp) << 4), bsrc + c * 4, 16);
    }

    cp_commit();
}

} // namespace

// ---- prologue: fp32 -> TF32(rna) conversion into __device__ scratch ----
__global__ __launch_bounds__(256)
void cvt_x_kernel(const float* __restrict__ src) {
    const int n4 = (H * W * CIN) / 4;
    int i = blockIdx.x * blockDim.x + threadIdx.x;
    if (i < n4) {
        float4 v = reinterpret_cast<const float4*>(src)[i];
        uint4 o = make_uint4(f2tf32(v.x), f2tf32(v.y), f2tf32(v.z), f2tf32(v.w));
        reinterpret_cast<uint4*>(Xc_g)[i] = o;
    }
}
__global__ __launch_bounds__(256)
void cvt_w_kernel(const float* __restrict__ src) {
    const int n4 = (COUT * KTOT) / 4;
    int i = blockIdx.x * blockDim.x + threadIdx.x;
    if (i < n4) {
        float4 v = reinterpret_cast<const float4*>(src)[i];
        uint4 o = make_uint4(f2tf32(v.x), f2tf32(v.y), f2tf32(v.z), f2tf32(v.w));
        reinterpret_cast<uint4*>(Wc_g)[i] = o;
    }
}

// ---- main GEMM ----
__global__ __launch_bounds__(512, 1)
void conv3x3_tc_kernel(float* __restrict__ Y) {
    extern __shared__ __align__(1024) uint32_t smem[];
    const uint32_t sbase = (uint32_t)__cvta_generic_to_shared(smem);

    const int tid  = threadIdx.x;
    const int warp = tid >> 5;
    const int lane = tid & 31;
    const int grp  = lane >> 2;
    const int tig  = lane & 3;

    const int mb = (warp & 3) * 64;      // 4 warps along m
    const int nb = (warp >> 2) * 32;     // 4 warps along n

    const int m0 = blockIdx.y * BM;
    const int n0 = blockIdx.x * BN;

    // ldmatrix lane geometry (XOR swizzle resolved per k-half in-loop).
    const int a_row = mb + (lane & 15);
    const int a_rp  = a_row & 7;
    const int a_h   = lane >> 4;
    const int b_row = nb + ((lane >> 4) << 3) + (lane & 7);
    const int b_rp  = b_row & 7;
    const int b_h   = (lane >> 3) & 1;

    // loader coordinates
    const int p  = m0 + (tid >> 1);
    const int ph = p / W;
    const int pw = p - ph * W;
    const uint32_t* wsrc = Wc_g + (long)(n0 + (tid >> 2)) * KTOT;

    float acc[4][4][4] = {};

    // Double-buffered fragments: [buf][...]
    uint32_t af[2][4][4], bf[2][4][2];

    // Per-khalf fragment fetch into buffer bsel.
    auto fetch_frags = [&](uint32_t astage, uint32_t bstage, int khalf, int bsel) {
        const int q = khalf * 2;
        const uint32_t a_co = (uint32_t)(((q + a_h) ^ a_rp) << 4);
        const uint32_t b_co = (uint32_t)(((q + b_h) ^ b_rp) << 4);
        #pragma unroll
        for (int mt = 0; mt < 4; ++mt)
            ldsm_x4(af[bsel][mt], astage + (uint32_t)((a_row + mt * 16) * ROWB) + a_co);
        #pragma unroll
        for (int np = 0; np < 2; ++np) {
            uint32_t tmp[4];
            ldsm_x4(tmp, bstage + (uint32_t)((b_row + np * 16) * ROWB) + b_co);
            bf[bsel][2 * np][0]     = tmp[0]; bf[bsel][2 * np][1]     = tmp[1];
            bf[bsel][2 * np + 1][0] = tmp[2]; bf[bsel][2 * np + 1][1] = tmp[3];
        }
    };

    #pragma unroll
    for (int t = 0; t < STAGES - 1; ++t) load_stage(t, sbase, tid, ph, pw, wsrc);

    for (int t = 0; t < NT; ++t) {
        cp_wait<STAGES - 2>();
        __syncthreads();

        const int slot = t & (STAGES - 1);
        const uint32_t astage = sbase + slot * STAGE_BYTES;
        const uint32_t bstage = astage + ABYTES;

        fetch_frags(astage, bstage, 0, 0);

        #pragma unroll
        for (int khalf = 0; khalf < 4; ++khalf) {
            const int cur = khalf & 1;
            // Prefetch next k-half's fragments BEFORE consuming current ones:
            // ldsm latency hides under the 64 mma below.
            if (khalf < 3) fetch_frags(astage, bstage, khalf + 1, cur ^ 1);
            #pragma unroll
            for (int mt = 0; mt < 4; ++mt)
                #pragma unroll
                for (int nt = 0; nt < 4; ++nt)
                    mma_tf32(acc[mt][nt], af[cur][mt], bf[cur][nt]);
        }

        if (t + STAGES - 1 < NT) load_stage(t + STAGES - 1, sbase, tid, ph, pw, wsrc);
    }

    // ---- epilogue: ReLU + STG.64 ----
    #pragma unroll
    for (int mt = 0; mt < 4; ++mt) {
        const int r0 = m0 + mb + mt * 16 + grp;
        #pragma unroll
        for (int nt = 0; nt < 4; ++nt) {
            const int cb = n0 + nb + nt * 8 + tig * 2;
            float2 o0, o1;
            o0.x = fmaxf(acc[mt][nt][0], 0.f);
            o0.y = fmaxf(acc[mt][nt][1], 0.f);
            o1.x = fmaxf(acc[mt][nt][2], 0.f);
            o1.y = fmaxf(acc[mt][nt][3], 0.f);
            *reinterpret_cast<float2*>(Y + (long)r0 * COUT + cb)       = o0;
            *reinterpret_cast<float2*>(Y + (long)(r0 + 8) * COUT + cb) = o1;
        }
    }
}

extern "C" void kernel_launch(void* const* d_in, const int* in_sizes, int n_in,
                              void* d_out, int out_size) {
    const float* X  = (const float*)d_in[0];
    const float* Wt = (const float*)d_in[1];
    float* Y        = (float*)d_out;

    cudaFuncSetAttribute(conv3x3_tc_kernel,
                         cudaFuncAttributeMaxDynamicSharedMemorySize, SMEM_TOTAL);

    const int nx4 = (H * W * CIN) / 4;
    const int nw4 = (COUT * KTOT) / 4;
    cvt_x_kernel<<<(nx4 + 255) / 256, 256>>>(X);
    cvt_w_kernel<<<(nw4 + 255) / 256, 256>>>(Wt);

    dim3 grid(COUT / BN, (H * W) / BM);   // (2, 196)
    conv3x3_tc_kernel<<<grid, 512, SMEM_TOTAL>>>(Y);
}